// round 9
// baseline (speedup 1.0000x reference)
#include <cuda_runtime.h>
#include <cstdint>

// Problem constants
#define B_   4
#define C_   512
#define C8_  64
#define H_   64
#define W_   64
#define HW_  4096

#define NBLK 1184  // 8 blocks/SM on 148 SMs; co-residency guaranteed:
                   //   launch_bounds(256,8) -> regs<=32
                   //   smem ~8.4KB/block (*8 = 67KB <= 228KB)
                   //   threads 2048/SM (the binding limit)

// Total elements: B*C*H*W = 8,388,608 floats = 2,097,152 float4
#define N_FLOAT4 ((size_t)2097152)

// Scratch (zero-initialized at module load; no runtime allocation)
__device__ float g_Q[(size_t)B_ * C8_ * HW_];          //  4 MB
__device__ float g_K[(size_t)B_ * C8_ * HW_];          //  4 MB  (K' = Wk x + bk + pos)
__device__ float g_V[(size_t)B_ * C_  * HW_];          // 32 MB
__device__ float g_S[(size_t)B_ * HW_ * HW_];          // 256 MB (energy / attention)

// Software grid barrier state (sense-reversal via generation counter)
__device__ unsigned g_bar_count = 0;
__device__ unsigned g_bar_gen   = 0;

__device__ __forceinline__ void grid_barrier()
{
    __threadfence();          // publish this thread's prior global writes
    __syncthreads();
    if (threadIdx.x == 0) {
        unsigned gen = *(volatile unsigned*)&g_bar_gen;
        if (atomicAdd(&g_bar_count, 1) == gridDim.x - 1) {
            g_bar_count = 0;
            __threadfence();
            atomicAdd(&g_bar_gen, 1);
        } else {
            while (*(volatile unsigned*)&g_bar_gen == gen) { }
        }
        __threadfence();      // acquire
    }
    __syncthreads();
}

// ---------------------------------------------------------------------------
// Single megakernel.
//   gamma == 0 : out = final_encoded (batched vectorized copy), return.
//   gamma != 0 : full attention pipeline in 4 phases with grid barriers.
// ---------------------------------------------------------------------------
__global__ __launch_bounds__(256, 8) void mega_kernel(
    const float* __restrict__ fin, const float* __restrict__ tot,
    const float* __restrict__ Wq, const float* __restrict__ bq,
    const float* __restrict__ Wk, const float* __restrict__ bk,
    const float* __restrict__ Wv, const float* __restrict__ bv,
    const float* __restrict__ hgt, const float* __restrict__ wdt,
    const float* __restrict__ gamma,
    float* __restrict__ out)
{
    const int tid = threadIdx.x;
    const float g = gamma[0];

    // ================= gamma == 0 fast path: pure copy =================
    if (g == 0.0f) {
        const float4* __restrict__ src = (const float4*)fin;
        float4* __restrict__ dst = (float4*)out;
        const size_t T = (size_t)NBLK * 256;                  // 303,104 threads
        const size_t i = (size_t)blockIdx.x * 256 + tid;
        // 6 unguarded strides: max idx = 5*T + (T-1) = 1,818,623 < 2,097,152.
        // Batched 3-load / 3-store for MLP.
        float4 a0 = src[i];
        float4 a1 = src[i + T];
        float4 a2 = src[i + 2 * T];
        dst[i]         = a0;
        dst[i + T]     = a1;
        dst[i + 2 * T] = a2;
        float4 a3 = src[i + 3 * T];
        float4 a4 = src[i + 4 * T];
        float4 a5 = src[i + 5 * T];
        dst[i + 3 * T] = a3;
        dst[i + 4 * T] = a4;
        dst[i + 5 * T] = a5;
        // Guarded tail: remainder 278,528 (< T) elements.
        const size_t j = i + 6 * T;
        if (j < N_FLOAT4) dst[j] = src[j];
        return;
    }

    // ================= gamma != 0: full attention pipeline =================
    // Max smem across phases: 2 * 16 * 65 floats = 8,320 B.
    __shared__ float sbuf[2 * 16 * 65];
    __shared__ float red[8];
    __shared__ float sval;

    const int tx = tid % 16, ty = tid / 16;

    // ---- Phase 1: projections Q (from total), K'(+pos), V (from final) ----
    {
        float* As = sbuf;            // As[kk][m] : [16][64]
        float* Bs = sbuf + 1024;     // Bs[kk][n] : [16][64]

        for (int t = blockIdx.x; t < 2560; t += gridDim.x) {
            const float *Wm, *bias, *X;
            float* Y;
            int b, m0, n0, MO;
            bool add_pos = false;
            if (t < 256) {
                b = t >> 6; n0 = (t & 63) << 6; m0 = 0; MO = C8_;
                Wm = Wq; bias = bq; X = tot; Y = g_Q;
            } else if (t < 512) {
                int u = t - 256;
                b = u >> 6; n0 = (u & 63) << 6; m0 = 0; MO = C8_;
                Wm = Wk; bias = bk; X = fin; Y = g_K; add_pos = true;
            } else {
                int u = t - 512;
                b = u >> 9; int rem = u & 511;
                m0 = (rem >> 6) << 6; n0 = (rem & 63) << 6; MO = C_;
                Wm = Wv; bias = bv; X = fin; Y = g_V;
            }
            const float* Xb = X + (size_t)b * C_ * HW_;
            float*       Yb = Y + (size_t)b * MO * HW_;

            float acc[4][4] = {};
            for (int k0 = 0; k0 < C_; k0 += 16) {
                #pragma unroll
                for (int i = 0; i < 4; i++) {
                    int idx = tid + i * 256;
                    int m = idx & 63, kk = idx >> 6;
                    As[kk * 64 + m] = Wm[(size_t)(m0 + m) * C_ + k0 + kk];
                }
                #pragma unroll
                for (int i = 0; i < 4; i++) {
                    int idx = tid + i * 256;
                    int n = idx & 63, kk = idx >> 6;
                    Bs[kk * 64 + n] = Xb[(size_t)(k0 + kk) * HW_ + n0 + n];
                }
                __syncthreads();
                #pragma unroll
                for (int kk = 0; kk < 16; kk++) {
                    float a[4], bb[4];
                    #pragma unroll
                    for (int i = 0; i < 4; i++) a[i]  = As[kk * 64 + ty * 4 + i];
                    #pragma unroll
                    for (int j = 0; j < 4; j++) bb[j] = Bs[kk * 64 + tx * 4 + j];
                    #pragma unroll
                    for (int i = 0; i < 4; i++)
                        #pragma unroll
                        for (int j = 0; j < 4; j++)
                            acc[i][j] += a[i] * bb[j];
                }
                __syncthreads();
            }

            #pragma unroll
            for (int i = 0; i < 4; i++) {
                int m = m0 + ty * 4 + i;
                float bv_ = bias[m];
                #pragma unroll
                for (int j = 0; j < 4; j++) {
                    int n = n0 + tx * 4 + j;
                    float val = acc[i][j] + bv_;
                    if (add_pos) {
                        int h = n >> 6, w = n & 63;
                        val += hgt[m * H_ + h] + wdt[m * W_ + w];
                    }
                    Yb[(size_t)m * HW_ + n] = val;
                }
            }
        }
    }
    grid_barrier();

    // ---- Phase 2: energy S[b,n,m] = sum_c Q[c,n] * K'[c,m] (16-deep tiles) ----
    {
        float* Qs = sbuf;            // Qs[kk][n] : [16][65]
        float* Ks = sbuf + 1040;     // Ks[kk][m] : [16][65]

        for (int t = blockIdx.x; t < 16384; t += gridDim.x) {
            const int b   = t >> 12;
            const int rem = t & 4095;
            const int n0  = (rem >> 6) << 6;
            const int m0  = (rem & 63) << 6;
            const float* Qb = g_Q + (size_t)b * C8_ * HW_;
            const float* Kb = g_K + (size_t)b * C8_ * HW_;
            float*       Sb = g_S + (size_t)b * HW_ * HW_;

            float acc[4][4] = {};
            for (int c0 = 0; c0 < C8_; c0 += 16) {
                #pragma unroll
                for (int i = 0; i < 4; i++) {
                    int idx = tid + i * 256;
                    int col = idx & 63, kk = idx >> 6;
                    Qs[kk * 65 + col] = Qb[(size_t)(c0 + kk) * HW_ + n0 + col];
                    Ks[kk * 65 + col] = Kb[(size_t)(c0 + kk) * HW_ + m0 + col];
                }
                __syncthreads();
                #pragma unroll
                for (int kk = 0; kk < 16; kk++) {
                    float a[4], bb[4];
                    #pragma unroll
                    for (int i = 0; i < 4; i++) a[i]  = Qs[kk * 65 + ty * 4 + i];
                    #pragma unroll
                    for (int j = 0; j < 4; j++) bb[j] = Ks[kk * 65 + tx * 4 + j];
                    #pragma unroll
                    for (int i = 0; i < 4; i++)
                        #pragma unroll
                        for (int j = 0; j < 4; j++)
                            acc[i][j] += a[i] * bb[j];
                }
                __syncthreads();
            }
            #pragma unroll
            for (int i = 0; i < 4; i++)
                #pragma unroll
                for (int j = 0; j < 4; j++)
                    Sb[(size_t)(n0 + ty * 4 + i) * HW_ + m0 + tx * 4 + j] = acc[i][j];
        }
    }
    grid_barrier();

    // ---- Phase 3: row softmax over last dim (4096) ----
    {
        for (int r = blockIdx.x; r < B_ * HW_; r += gridDim.x) {
            float* row = g_S + (size_t)r * HW_;

            float v[16];
            float mx = -1e30f;
            #pragma unroll
            for (int i = 0; i < 16; i++) { v[i] = row[tid + i * 256]; mx = fmaxf(mx, v[i]); }

            #pragma unroll
            for (int o = 16; o > 0; o >>= 1) mx = fmaxf(mx, __shfl_xor_sync(0xffffffffu, mx, o));
            if ((tid & 31) == 0) red[tid >> 5] = mx;
            __syncthreads();
            if (tid == 0) {
                float m = red[0];
                #pragma unroll
                for (int i = 1; i < 8; i++) m = fmaxf(m, red[i]);
                sval = m;
            }
            __syncthreads();
            mx = sval;

            float s = 0.0f;
            #pragma unroll
            for (int i = 0; i < 16; i++) { v[i] = __expf(v[i] - mx); s += v[i]; }
            #pragma unroll
            for (int o = 16; o > 0; o >>= 1) s += __shfl_xor_sync(0xffffffffu, s, o);
            __syncthreads();
            if ((tid & 31) == 0) red[tid >> 5] = s;
            __syncthreads();
            if (tid == 0) {
                float tsum = 0.0f;
                #pragma unroll
                for (int i = 0; i < 8; i++) tsum += red[i];
                sval = tsum;
            }
            __syncthreads();
            const float inv = 1.0f / sval;

            #pragma unroll
            for (int i = 0; i < 16; i++) row[tid + i * 256] = v[i] * inv;
            __syncthreads();
        }
    }
    grid_barrier();

    // ---- Phase 4: out[b,c,n] = g * sum_m V[c,m]*A[n,m] + fin[b,c,n] ----
    {
        float* As = sbuf;            // As[kk][c] : [16][65]
        float* Bs = sbuf + 1040;     // Bs[kk][n] : [16][65]

        for (int t = blockIdx.x; t < 2048; t += gridDim.x) {
            const int b   = t >> 9;
            const int rem = t & 511;
            const int c0  = (rem >> 6) << 6;
            const int n0  = (rem & 63) << 6;
            const float* Vb = g_V + (size_t)b * C_ * HW_;
            const float* Sb = g_S + (size_t)b * HW_ * HW_;
            const float* Fb = fin + (size_t)b * C_ * HW_;
            float*       Ob = out + (size_t)b * C_ * HW_;

            float acc[4][4] = {};
            for (int mk = 0; mk < HW_; mk += 16) {
                #pragma unroll
                for (int i = 0; i < 4; i++) {
                    int idx = tid + i * 256;
                    int kk = idx & 15, rr = idx >> 4;
                    As[kk * 65 + rr] = Vb[(size_t)(c0 + rr) * HW_ + mk + kk];
                    Bs[kk * 65 + rr] = Sb[(size_t)(n0 + rr) * HW_ + mk + kk];
                }
                __syncthreads();
                #pragma unroll
                for (int kk = 0; kk < 16; kk++) {
                    float a[4], bb[4];
                    #pragma unroll
                    for (int i = 0; i < 4; i++) a[i]  = As[kk * 65 + ty * 4 + i];
                    #pragma unroll
                    for (int j = 0; j < 4; j++) bb[j] = Bs[kk * 65 + tx * 4 + j];
                    #pragma unroll
                    for (int i = 0; i < 4; i++)
                        #pragma unroll
                        for (int j = 0; j < 4; j++)
                            acc[i][j] += a[i] * bb[j];
                }
                __syncthreads();
            }

            #pragma unroll
            for (int i = 0; i < 4; i++) {
                int c = c0 + ty * 4 + i;
                #pragma unroll
                for (int j = 0; j < 4; j++) {
                    int n = n0 + tx * 4 + j;
                    size_t off = (size_t)c * HW_ + n;
                    Ob[off] = g * acc[i][j] + Fb[off];
                }
            }
        }
    }
}

// ---------------------------------------------------------------------------
extern "C" void kernel_launch(void* const* d_in, const int* in_sizes, int n_in,
                              void* d_out, int out_size)
{
    const float* fin   = (const float*)d_in[0];
    const float* tot   = (const float*)d_in[1];
    const float* Wq    = (const float*)d_in[2];
    const float* bq    = (const float*)d_in[3];
    const float* Wk    = (const float*)d_in[4];
    const float* bk    = (const float*)d_in[5];
    const float* Wv    = (const float*)d_in[6];
    const float* bv    = (const float*)d_in[7];
    const float* hgt   = (const float*)d_in[8];
    const float* wdt   = (const float*)d_in[9];
    const float* gamma = (const float*)d_in[10];
    float* out = (float*)d_out;

    mega_kernel<<<NBLK, 256>>>(fin, tot, Wq, bq, Wk, bk, Wv, bv,
                               hgt, wdt, gamma, out);
}